// round 1
// baseline (speedup 1.0000x reference)
#include <cuda_runtime.h>
#include <math.h>

#define BATCH   4
#define SEQ     2048
#define DMODEL  1024
#define DINNER  2048
#define DSTATE  64
#define MROWS   (BATCH*SEQ)      /* 8192 */
#define NPROJ   (2*DSTATE+1)     /* 129  */

// ---------------- scratch (device globals; no allocations allowed) ----------
__device__ float g_xi  [MROWS*DINNER];   // x-branch of input proj
__device__ float g_sz  [MROWS*DINNER];   // silu(z)
__device__ float g_bx  [MROWS*DINNER];   // B * xi  (scan b-term)
__device__ float g_Cm  [MROWS*DINNER];   // C matrix
__device__ float g_y   [MROWS*DINNER];   // pre-output activations
__device__ float g_proj[MROWS*NPROJ];    // [delta_raw | B_raw | C_raw]
__device__ float g_a   [MROWS];          // A_bar per (b,s)

// ---------------- packed f32x2 helpers (Blackwell FFMA2) --------------------
__device__ __forceinline__ unsigned long long pack2(float lo, float hi) {
    unsigned long long r;
    asm("mov.b64 %0,{%1,%2};" : "=l"(r) : "f"(lo), "f"(hi));
    return r;
}
__device__ __forceinline__ void unpack2(unsigned long long v, float& lo, float& hi) {
    asm("mov.b64 {%0,%1},%2;" : "=f"(lo), "=f"(hi) : "l"(v));
}
__device__ __forceinline__ void fma2(unsigned long long& d,
                                     unsigned long long a,
                                     unsigned long long b) {
    asm("fma.rn.f32x2 %0,%1,%2,%0;" : "+l"(d) : "l"(a), "l"(b));
}

// ---------------- generic 128x128x16 GEMM, 8x8 microtile, FFMA2 -------------
// MODE 0: C0[m,n] = sum
// MODE 1: split epilogue: n <  DINNER -> C0 = v (xi)
//                         n >= DINNER -> C1 = silu(v)
// MODE 2: C0 = v * aux[m,n]   (B * xi fusion)
template <int MODE>
__global__ __launch_bounds__(256)
void gemm_kernel(const float* __restrict__ A, int lda,
                 const float* __restrict__ B, int ldb,
                 float* __restrict__ C0, float* __restrict__ C1,
                 const float* __restrict__ aux,
                 int M, int N, int K)
{
    constexpr int BM = 128, BN = 128, BK = 16;
    __shared__ float As[BK][BM + 4];   // stride 132 (pad vs STS conflicts)
    __shared__ float Bs[BK][BN];

    const int t  = threadIdx.x;
    const int tx = t & 15;             // column group
    const int ty = t >> 4;             // row group
    const int rowBase = blockIdx.y * BM;
    const int colBase = blockIdx.x * BN;

    unsigned long long acc[8][4];
#pragma unroll
    for (int i = 0; i < 8; i++)
#pragma unroll
        for (int j = 0; j < 4; j++) acc[i][j] = 0ull;

    for (int k0 = 0; k0 < K; k0 += BK) {
        // load A tile (128x16), transposed into smem
#pragma unroll
        for (int e = 0; e < 8; e++) {
            int id = t + 256 * e;
            int r = id >> 4, c = id & 15;
            As[c][r] = A[(size_t)(rowBase + r) * lda + (k0 + c)];
        }
        // load B tile (16x128)
#pragma unroll
        for (int e = 0; e < 8; e++) {
            int id = t + 256 * e;
            int r = id >> 7, c = id & 127;
            Bs[r][c] = B[(size_t)(k0 + r) * ldb + (colBase + c)];
        }
        __syncthreads();

#pragma unroll
        for (int kk = 0; kk < BK; kk++) {
            float a8[8], b8[8];
#pragma unroll
            for (int i = 0; i < 8; i++) a8[i] = As[kk][ty * 8 + i];
#pragma unroll
            for (int j = 0; j < 8; j++) b8[j] = Bs[kk][tx * 8 + j];
            unsigned long long bp[4];
#pragma unroll
            for (int j = 0; j < 4; j++) bp[j] = pack2(b8[2 * j], b8[2 * j + 1]);
#pragma unroll
            for (int i = 0; i < 8; i++) {
                unsigned long long ap = pack2(a8[i], a8[i]);
#pragma unroll
                for (int j = 0; j < 4; j++) fma2(acc[i][j], ap, bp[j]);
            }
        }
        __syncthreads();
    }

    // epilogue
#pragma unroll
    for (int i = 0; i < 8; i++) {
        int gr = rowBase + ty * 8 + i;
#pragma unroll
        for (int j = 0; j < 4; j++) {
            float v0, v1;
            unpack2(acc[i][j], v0, v1);
            int gc = colBase + tx * 8 + 2 * j;
#pragma unroll
            for (int u = 0; u < 2; u++) {
                float v  = (u == 0) ? v0 : v1;
                int   nc = gc + u;
                if (MODE == 0) {
                    C0[(size_t)gr * N + nc] = v;
                } else if (MODE == 1) {
                    if (nc < DINNER) {
                        C0[(size_t)gr * DINNER + nc] = v;
                    } else {
                        float s = v / (1.0f + expf(-v));        // silu
                        C1[(size_t)gr * DINNER + (nc - DINNER)] = s;
                    }
                } else { // MODE 2
                    size_t idx = (size_t)gr * N + nc;
                    C0[idx] = v * aux[idx];
                }
            }
        }
    }
}

// ---------------- proj = xi @ W_xp   (N = 129, tall-skinny) -----------------
__global__ __launch_bounds__(256)
void proj_kernel(const float* __restrict__ xi,
                 const float* __restrict__ W,
                 float* __restrict__ proj)
{
    __shared__ float xs[32][65];     // [k][row], padded
    __shared__ float ws[32][132];    // [k][col], padded

    const int t  = threadIdx.x;
    const int tx = t & 31;           // col lane
    const int ty = t >> 5;           // row group (8 rows each)
    const int rowBase = blockIdx.x * 64;

    float acc[8][5];
#pragma unroll
    for (int i = 0; i < 8; i++)
#pragma unroll
        for (int j = 0; j < 5; j++) acc[i][j] = 0.0f;

    for (int k0 = 0; k0 < DINNER; k0 += 32) {
#pragma unroll
        for (int e = 0; e < 8; e++) {
            int id = t + 256 * e;
            int r = id >> 5, c = id & 31;
            xs[c][r] = xi[(size_t)(rowBase + r) * DINNER + (k0 + c)];
        }
        for (int id = t; id < 32 * NPROJ; id += 256) {
            int kk = id / NPROJ, c = id % NPROJ;
            ws[kk][c] = W[(size_t)(k0 + kk) * NPROJ + c];
        }
        __syncthreads();

#pragma unroll
        for (int kk = 0; kk < 32; kk++) {
            float a8[8];
#pragma unroll
            for (int i = 0; i < 8; i++) a8[i] = xs[kk][ty * 8 + i];
#pragma unroll
            for (int j = 0; j < 5; j++) {
                int cj = tx + 32 * j;
                float w = (cj < NPROJ) ? ws[kk][cj] : 0.0f;
#pragma unroll
                for (int i = 0; i < 8; i++) acc[i][j] += a8[i] * w;
            }
        }
        __syncthreads();
    }

#pragma unroll
    for (int i = 0; i < 8; i++) {
        int gr = rowBase + ty * 8 + i;
#pragma unroll
        for (int j = 0; j < 5; j++) {
            int cj = tx + 32 * j;
            if (cj < NPROJ) proj[(size_t)gr * NPROJ + cj] = acc[i][j];
        }
    }
}

// ---------------- delta -> A_bar per (b,s) ----------------------------------
__global__ void delta_kernel(const float* __restrict__ proj,
                             const float* __restrict__ A_log,
                             float* __restrict__ ga)
{
    int m = blockIdx.x * blockDim.x + threadIdx.x;
    if (m < MROWS) {
        float x = proj[(size_t)m * NPROJ];                 // delta pre-activation
        float sp = (x > 20.0f) ? x : log1pf(expf(x));      // softplus
        float A = -expf(A_log[0]);
        ga[m] = expf(sp * A);
    }
}

// ---------------- sequential scan + fused epilogue --------------------------
// h_t = a_t * h_{t-1} + (B*xi)_t ;  y = (C*h + D*xi) * silu(z)
__global__ __launch_bounds__(128)
void scan_kernel(const float* __restrict__ D)
{
    int b = blockIdx.x >> 4;                         // 4 batches
    int d = (blockIdx.x & 15) * 128 + threadIdx.x;   // 16*128 = 2048 channels
    float Dd = D[d];
    float h = 0.0f;
    size_t base = (size_t)b * SEQ * DINNER + d;
    int arow = b * SEQ;
#pragma unroll 4
    for (int s = 0; s < SEQ; s++) {
        size_t idx = base + (size_t)s * DINNER;
        float a  = g_a[arow + s];
        float xi = g_xi[idx];
        h = fmaf(a, h, g_bx[idx]);
        float y = fmaf(g_Cm[idx], h, Dd * xi);
        g_y[idx] = y * g_sz[idx];
    }
}

// ---------------- launch ----------------------------------------------------
extern "C" void kernel_launch(void* const* d_in, const int* in_sizes, int n_in,
                              void* d_out, int out_size)
{
    const float* x     = (const float*)d_in[0];
    const float* W_in  = (const float*)d_in[1];
    const float* W_xp  = (const float*)d_in[2];
    const float* W_B   = (const float*)d_in[3];
    const float* W_C   = (const float*)d_in[4];
    const float* W_out = (const float*)d_in[5];
    const float* Dvec  = (const float*)d_in[6];
    const float* A_log = (const float*)d_in[7];
    float* out = (float*)d_out;

    float *p_xi, *p_sz, *p_bx, *p_Cm, *p_y, *p_proj, *p_a;
    cudaGetSymbolAddress((void**)&p_xi,   g_xi);
    cudaGetSymbolAddress((void**)&p_sz,   g_sz);
    cudaGetSymbolAddress((void**)&p_bx,   g_bx);
    cudaGetSymbolAddress((void**)&p_Cm,   g_Cm);
    cudaGetSymbolAddress((void**)&p_y,    g_y);
    cudaGetSymbolAddress((void**)&p_proj, g_proj);
    cudaGetSymbolAddress((void**)&p_a,    g_a);

    // 1) xz = x @ W_in, fused split into xi and silu(z)
    gemm_kernel<1><<<dim3(4096 / 128, MROWS / 128), 256>>>(
        x, DMODEL, W_in, 2 * DINNER, p_xi, p_sz, nullptr,
        MROWS, 2 * DINNER, DMODEL);

    // 2) proj = xi @ W_xp  (N = 129)
    proj_kernel<<<MROWS / 64, 256>>>(p_xi, W_xp, p_proj);

    // 3) delta -> A_bar
    delta_kernel<<<MROWS / 256, 256>>>(p_proj, A_log, p_a);

    // 4) B = B_raw @ W_B, fused * xi  -> g_bx
    gemm_kernel<2><<<dim3(DINNER / 128, MROWS / 128), 256>>>(
        p_proj + 1, NPROJ, W_B, DINNER, p_bx, nullptr, p_xi,
        MROWS, DINNER, DSTATE);

    // 5) C = C_raw @ W_C -> g_Cm
    gemm_kernel<0><<<dim3(DINNER / 128, MROWS / 128), 256>>>(
        p_proj + 1 + DSTATE, NPROJ, W_C, DINNER, p_Cm, nullptr, nullptr,
        MROWS, DINNER, DSTATE);

    // 6) sequential scan + fused (C*h + D*xi)*silu(z)
    scan_kernel<<<BATCH * (DINNER / 128), 128>>>(Dvec);

    // 7) out = y @ W_out
    gemm_kernel<0><<<dim3(DMODEL / 128, MROWS / 128), 256>>>(
        p_y, DINNER, W_out, DMODEL, out, nullptr, nullptr,
        MROWS, DMODEL, DINNER);
}

// round 3
// speedup vs baseline: 1.8577x; 1.8577x over previous
#include <cuda_runtime.h>
#include <cstdint>
#include <math.h>

#define BATCH   4
#define SEQ     2048
#define DMODEL  1024
#define DINNER  2048
#define DSTATE  64
#define MROWS   (BATCH*SEQ)      /* 8192 */
#define NPROJ   (2*DSTATE+1)     /* 129  */

// ---------------- scratch (device globals; no allocations allowed) ----------
__device__ float g_xi [MROWS*DINNER];   // x-branch of input proj
__device__ float g_sz [MROWS*DINNER];   // silu(z)
__device__ float g_bx [MROWS*DINNER];   // B * xi (scan b-term)
__device__ float g_Cm [MROWS*DINNER];   // C matrix
__device__ float g_y  [MROWS*DINNER];   // pre-output activations
__device__ float g_pBC[MROWS*128];      // [B_raw | C_raw]
__device__ float g_a  [MROWS];          // A_bar per (b,s)

// ---------------- helpers ---------------------------------------------------
__device__ __forceinline__ uint32_t to_tf32_bits(float x) {
    float y;
    asm("cvt.rna.tf32.f32 %0, %1;" : "=f"(y) : "f"(x));
    return __float_as_uint(y);
}

__device__ __forceinline__ void mma_m16n8k8(float* c, const uint32_t* a, const uint32_t* b) {
    asm volatile(
        "mma.sync.aligned.m16n8k8.row.col.f32.tf32.tf32.f32 "
        "{%0,%1,%2,%3}, {%4,%5,%6,%7}, {%8,%9}, {%0,%1,%2,%3};"
        : "+f"(c[0]), "+f"(c[1]), "+f"(c[2]), "+f"(c[3])
        : "r"(a[0]), "r"(a[1]), "r"(a[2]), "r"(a[3]), "r"(b[0]), "r"(b[1]));
}

// ======================= tf32 mma.sync GEMM =================================
// C[M,N] = A[M,K] @ B[K,N].  Block tile 128x128, BK=32, 256 thr (8 warps).
// Warp tile 32(M) x 64(N): 2 m-subtiles x 8 n-subtiles of m16n8k8.
// MODE 0: C0 = v
// MODE 1: col < DINNER -> C0 = v (xi) ; col >= DINNER -> C1 = silu(v)
// MODE 2: C0 = v * aux
template <int MODE, bool BVEC>
__global__ __launch_bounds__(256)
void gemm_mma(const float* __restrict__ A, int lda,
              const float* __restrict__ B, int ldb,
              float* __restrict__ C0, float* __restrict__ C1,
              const float* __restrict__ aux, int N, int K)
{
    __shared__ float As[32][133];   // [k][m], stride 133 -> conflict-free STS
    __shared__ float Bs[32][132];   // [k][n]

    const int t    = threadIdx.x;
    const int lane = t & 31;
    const int wid  = t >> 5;
    const int warpM = wid & 3;      // 4 warps over M (32 rows each)
    const int warpN = wid >> 2;     // 2 warps over N (64 cols each)
    const int rowBase = blockIdx.y * 128;
    const int colBase = blockIdx.x * 128;

    float acc[2][8][4];
#pragma unroll
    for (int i = 0; i < 2; i++)
#pragma unroll
        for (int j = 0; j < 8; j++)
#pragma unroll
            for (int q = 0; q < 4; q++) acc[i][j][q] = 0.0f;

    // prefetch registers
    float4 ra[4];            // A tile: thread covers 4 float4 (rows id>>3, kq id&7)
    float4 rb4[4];           // B tile (vector path)
    float  rbs[16];          // B tile (scalar path, ldb misaligned)

    const int nkt = K / 32;

    // ---- load tile kt into regs
    auto loadA = [&](int kt) {
        const int k0 = kt * 32;
#pragma unroll
        for (int e = 0; e < 4; e++) {
            int id = t + 256 * e;
            int r = id >> 3, q = id & 7;
            ra[e] = *reinterpret_cast<const float4*>(
                A + (size_t)(rowBase + r) * lda + k0 + q * 4);
        }
    };
    auto loadB = [&](int kt) {
        const int k0 = kt * 32;
        if (BVEC) {
#pragma unroll
            for (int e = 0; e < 4; e++) {
                int k = (t >> 5) + 8 * e;
                int n = (t & 31) * 4;
                rb4[e] = *reinterpret_cast<const float4*>(
                    B + (size_t)(k0 + k) * ldb + colBase + n);
            }
        } else {
#pragma unroll
            for (int e = 0; e < 16; e++) {
                int id = t + 256 * e;
                int k = id >> 7, n = id & 127;
                rbs[e] = B[(size_t)(k0 + k) * ldb + colBase + n];
            }
        }
    };
    auto stsTile = [&]() {
#pragma unroll
        for (int e = 0; e < 4; e++) {
            int id = t + 256 * e;
            int r = id >> 3, q = id & 7;
            As[q * 4 + 0][r] = __uint_as_float(to_tf32_bits(ra[e].x));
            As[q * 4 + 1][r] = __uint_as_float(to_tf32_bits(ra[e].y));
            As[q * 4 + 2][r] = __uint_as_float(to_tf32_bits(ra[e].z));
            As[q * 4 + 3][r] = __uint_as_float(to_tf32_bits(ra[e].w));
        }
        if (BVEC) {
#pragma unroll
            for (int e = 0; e < 4; e++) {
                int k = (t >> 5) + 8 * e;
                int n = (t & 31) * 4;
                Bs[k][n + 0] = __uint_as_float(to_tf32_bits(rb4[e].x));
                Bs[k][n + 1] = __uint_as_float(to_tf32_bits(rb4[e].y));
                Bs[k][n + 2] = __uint_as_float(to_tf32_bits(rb4[e].z));
                Bs[k][n + 3] = __uint_as_float(to_tf32_bits(rb4[e].w));
            }
        } else {
#pragma unroll
            for (int e = 0; e < 16; e++) {
                int id = t + 256 * e;
                int k = id >> 7, n = id & 127;
                Bs[k][n] = __uint_as_float(to_tf32_bits(rbs[e]));
            }
        }
    };

    loadA(0); loadB(0);

    for (int kt = 0; kt < nkt; kt++) {
        stsTile();
        __syncthreads();
        if (kt + 1 < nkt) { loadA(kt + 1); loadB(kt + 1); }

        const int mrow = warpM * 32 + (lane >> 2);
        const int ncol = warpN * 64 + (lane >> 2);
        const int kq   = lane & 3;
#pragma unroll
        for (int ks = 0; ks < 4; ks++) {
            const int kb = ks * 8;
            uint32_t af[2][4];
#pragma unroll
            for (int mt = 0; mt < 2; mt++) {
                int r = mrow + mt * 16;
                af[mt][0] = __float_as_uint(As[kb + kq][r]);
                af[mt][1] = __float_as_uint(As[kb + kq][r + 8]);
                af[mt][2] = __float_as_uint(As[kb + kq + 4][r]);
                af[mt][3] = __float_as_uint(As[kb + kq + 4][r + 8]);
            }
            uint32_t bf[8][2];
#pragma unroll
            for (int nt = 0; nt < 8; nt++) {
                int c = ncol + nt * 8;
                bf[nt][0] = __float_as_uint(Bs[kb + kq][c]);
                bf[nt][1] = __float_as_uint(Bs[kb + kq + 4][c]);
            }
#pragma unroll
            for (int mt = 0; mt < 2; mt++)
#pragma unroll
                for (int nt = 0; nt < 8; nt++)
                    mma_m16n8k8(acc[mt][nt], af[mt], bf[nt]);
        }
        __syncthreads();
    }

    // ---- epilogue: direct float2 stores
    float* C = C0;
    int cbase = colBase;
    bool do_silu = false;
    int cstride = N;
    if (MODE == 1) {
        cstride = DINNER;
        if (colBase >= DINNER) { C = C1; cbase = colBase - DINNER; do_silu = true; }
    }

#pragma unroll
    for (int mt = 0; mt < 2; mt++) {
#pragma unroll
        for (int nt = 0; nt < 8; nt++) {
            int gr = rowBase + warpM * 32 + mt * 16 + (lane >> 2);
            int gc = cbase + warpN * 64 + nt * 8 + 2 * (lane & 3);
#pragma unroll
            for (int h = 0; h < 2; h++) {   // h=0: rows gr, h=1: rows gr+8
                float v0 = acc[mt][nt][2 * h];
                float v1 = acc[mt][nt][2 * h + 1];
                int r = gr + h * 8;
                if (MODE == 1 && do_silu) {
                    v0 = v0 / (1.0f + expf(-v0));
                    v1 = v1 / (1.0f + expf(-v1));
                }
                if (MODE == 2) {
                    float2 a2 = *reinterpret_cast<const float2*>(aux + (size_t)r * N + gc);
                    v0 *= a2.x; v1 *= a2.y;
                }
                float2 o; o.x = v0; o.y = v1;
                *reinterpret_cast<float2*>(C + (size_t)r * cstride + gc) = o;
            }
        }
    }
}

// ---------------- delta: softplus(xi . W_xp[:,0]) -> A_bar ------------------
__global__ __launch_bounds__(256)
void delta_kernel(const float* __restrict__ xi, const float* __restrict__ W,
                  const float* __restrict__ A_log, float* __restrict__ ga)
{
    int m = blockIdx.x;
    const float* row = xi + (size_t)m * DINNER;
    float s = 0.0f;
    for (int k = threadIdx.x; k < DINNER; k += 256)
        s += row[k] * W[(size_t)k * NPROJ];
#pragma unroll
    for (int o = 16; o; o >>= 1) s += __shfl_xor_sync(0xFFFFFFFFu, s, o);
    __shared__ float red[8];
    if ((threadIdx.x & 31) == 0) red[threadIdx.x >> 5] = s;
    __syncthreads();
    if (threadIdx.x == 0) {
        float v = 0.0f;
#pragma unroll
        for (int i = 0; i < 8; i++) v += red[i];
        float sp = (v > 20.0f) ? v : log1pf(expf(v));
        ga[m] = expf(-expf(A_log[0]) * sp);
    }
}

// ---------------- sequential scan + fused epilogue --------------------------
// h_t = a_t * h_{t-1} + (B*xi)_t ;  y = (C*h + D*xi) * silu(z)
__global__ __launch_bounds__(128)
void scan_kernel(const float* __restrict__ D)
{
    int b = blockIdx.x >> 4;
    int d = (blockIdx.x & 15) * 128 + threadIdx.x;
    float Dd = D[d];
    float h = 0.0f;
    size_t base = (size_t)b * SEQ * DINNER + d;
    int arow = b * SEQ;
#pragma unroll 8
    for (int s = 0; s < SEQ; s++) {
        size_t idx = base + (size_t)s * DINNER;
        float a  = g_a[arow + s];
        float xi = g_xi[idx];
        h = fmaf(a, h, g_bx[idx]);
        float y = fmaf(g_Cm[idx], h, Dd * xi);
        g_y[idx] = y * g_sz[idx];
    }
}

// ---------------- launch ----------------------------------------------------
extern "C" void kernel_launch(void* const* d_in, const int* in_sizes, int n_in,
                              void* d_out, int out_size)
{
    const float* x     = (const float*)d_in[0];
    const float* W_in  = (const float*)d_in[1];
    const float* W_xp  = (const float*)d_in[2];
    const float* W_B   = (const float*)d_in[3];
    const float* W_C   = (const float*)d_in[4];
    const float* W_out = (const float*)d_in[5];
    const float* Dvec  = (const float*)d_in[6];
    const float* A_log = (const float*)d_in[7];
    float* out = (float*)d_out;

    float *p_xi, *p_sz, *p_bx, *p_Cm, *p_y, *p_pBC, *p_a;
    cudaGetSymbolAddress((void**)&p_xi,  g_xi);
    cudaGetSymbolAddress((void**)&p_sz,  g_sz);
    cudaGetSymbolAddress((void**)&p_bx,  g_bx);
    cudaGetSymbolAddress((void**)&p_Cm,  g_Cm);
    cudaGetSymbolAddress((void**)&p_y,   g_y);
    cudaGetSymbolAddress((void**)&p_pBC, g_pBC);
    cudaGetSymbolAddress((void**)&p_a,   g_a);

    // 1) xz = x @ W_in, fused split -> xi, silu(z)
    gemm_mma<1, true><<<dim3(4096 / 128, 64), 256>>>(
        x, DMODEL, W_in, 2 * DINNER, p_xi, p_sz, nullptr, 2 * DINNER, DMODEL);

    // 2) delta column -> A_bar
    delta_kernel<<<MROWS, 256>>>(p_xi, W_xp, A_log, p_a);

    // 3) [B_raw|C_raw] = xi @ W_xp[:,1:129]  (N = 128, ldb=129 -> scalar B)
    gemm_mma<0, false><<<dim3(1, 64), 256>>>(
        p_xi, DINNER, W_xp + 1, NPROJ, p_pBC, nullptr, nullptr, 128, DINNER);

    // 4) bx = (B_raw @ W_B) * xi
    gemm_mma<2, true><<<dim3(DINNER / 128, 64), 256>>>(
        p_pBC, 128, W_B, DINNER, p_bx, nullptr, p_xi, DINNER, DSTATE);

    // 5) Cm = C_raw @ W_C
    gemm_mma<0, true><<<dim3(DINNER / 128, 64), 256>>>(
        p_pBC + 64, 128, W_C, DINNER, p_Cm, nullptr, nullptr, DINNER, DSTATE);

    // 6) scan + fused (C*h + D*xi)*silu(z)
    scan_kernel<<<BATCH * (DINNER / 128), 128>>>(Dvec);

    // 7) out = y @ W_out
    gemm_mma<0, true><<<dim3(DMODEL / 128, 64), 256>>>(
        p_y, DINNER, W_out, DMODEL, out, nullptr, nullptr, DMODEL, DINNER);
}

// round 4
// speedup vs baseline: 4.2565x; 2.2912x over previous
#include <cuda_runtime.h>
#include <cstdint>
#include <math.h>

#define BATCH   4
#define SEQ     2048
#define DMODEL  1024
#define DINNER  2048
#define DSTATE  64
#define MROWS   (BATCH*SEQ)      /* 8192 */
#define NPROJ   (2*DSTATE+1)     /* 129  */
#define NCH     16               /* scan chunks */
#define CHLEN   (SEQ/NCH)        /* 128 */

// ---------------- scratch (device globals; no allocations allowed) ----------
__device__ float g_xi  [MROWS*DINNER];
__device__ float g_sz  [MROWS*DINNER];
__device__ float g_bx  [MROWS*DINNER];
__device__ float g_Cm  [MROWS*DINNER];
__device__ float g_y   [MROWS*DINNER];
__device__ float g_pBC [MROWS*128];
__device__ float g_a   [MROWS];
__device__ float g_hend [BATCH*NCH*DINNER];
__device__ float g_carry[BATCH*NCH*DINNER];
__device__ float g_prodA[BATCH*NCH];

// ---------------- helpers ---------------------------------------------------
__device__ __forceinline__ uint32_t smem_u32(const void* p) {
    uint32_t a;
    asm("{ .reg .u64 t; cvta.to.shared.u64 t, %1; cvt.u32.u64 %0, t; }" : "=r"(a) : "l"(p));
    return a;
}
__device__ __forceinline__ float tf32r(float x) {
    float y; asm("cvt.rna.tf32.f32 %0, %1;" : "=f"(y) : "f"(x)); return y;
}
__device__ __forceinline__ void cp16(uint32_t s, const void* g) {
    asm volatile("cp.async.cg.shared.global [%0], [%1], 16;" :: "r"(s), "l"(g));
}
__device__ __forceinline__ void cp4(uint32_t s, const void* g) {
    asm volatile("cp.async.ca.shared.global [%0], [%1], 4;" :: "r"(s), "l"(g));
}
#define CP_COMMIT asm volatile("cp.async.commit_group;" ::: "memory")
#define CP_WAIT1  asm volatile("cp.async.wait_group 1;" ::: "memory")
#define CP_WAIT0  asm volatile("cp.async.wait_group 0;" ::: "memory")

__device__ __forceinline__ void mma8(float* c, const uint32_t* a, const uint32_t* b) {
    asm volatile(
        "mma.sync.aligned.m16n8k8.row.col.f32.tf32.tf32.f32 "
        "{%0,%1,%2,%3}, {%4,%5,%6,%7}, {%8,%9}, {%0,%1,%2,%3};"
        : "+f"(c[0]), "+f"(c[1]), "+f"(c[2]), "+f"(c[3])
        : "r"(a[0]), "r"(a[1]), "r"(a[2]), "r"(a[3]), "r"(b[0]), "r"(b[1]));
}

// ======================= tf32 mma.sync GEMM, cp.async 2-stage ===============
// C[M,N] = A[M,K+] @ B[K+,N] over K (per-block chunk via blockIdx.z*K offset)
// Block tile 128x128, BK=32, 256 thr.  Warp tile 32(M) x 64(N).
// smem: As[2][128][36], Bs[2][32][136]   (dynamic, 71680 B)
// MODE 0: C0=v   MODE 1: split xi / silu(z)   MODE 2: C0=v*aux
// MODE 3: atomicAdd(C0, v)   (split-K)
// PRECISE: 3xtf32 (hi/lo split of both operands)
#define A_STG 18432u
#define B_STG 17408u
#define SB_OFF 36864u
#define GEMM_SMEM 71680

template <int MODE, bool PRECISE, bool BALIGN>
__global__ void
#if 1
__launch_bounds__(256, 2)
#endif
gemm_cp(const float* __restrict__ A, int lda,
        const float* __restrict__ B, int ldb,
        float* __restrict__ C0, float* __restrict__ C1,
        const float* __restrict__ aux, int N, int K)
{
    extern __shared__ char smem[];
    const uint32_t sA = smem_u32(smem);
    const uint32_t sB = sA + SB_OFF;
    float* fs = (float*)smem;

    const int t    = threadIdx.x;
    const int lane = t & 31;
    const int wid  = t >> 5;
    const int warpM = wid & 3;
    const int warpN = wid >> 2;
    const int rowBase = blockIdx.y * 128;
    const int colBase = blockIdx.x * 128;
    const int kBase   = blockIdx.z * K;

    float acc[2][8][4];
#pragma unroll
    for (int i = 0; i < 2; i++)
#pragma unroll
        for (int j = 0; j < 8; j++)
#pragma unroll
            for (int q = 0; q < 4; q++) acc[i][j][q] = 0.0f;

    const int nkt = K / 32;

    auto issue = [&](int st, int kt) {
        const int k0 = kBase + kt * 32;
        // A: 128 rows x 32 floats = 1024 x 16B chunks, 4/thread
#pragma unroll
        for (int e = 0; e < 4; e++) {
            int id = t + 256 * e;
            int r = id >> 3, q = id & 7;
            cp16(sA + st * A_STG + (uint32_t)(r * 36 + q * 4) * 4,
                 A + (size_t)(rowBase + r) * lda + k0 + q * 4);
        }
        if (BALIGN) {
#pragma unroll
            for (int e = 0; e < 4; e++) {
                int id = t + 256 * e;
                int k = id >> 5, q = id & 31;
                cp16(sB + st * B_STG + (uint32_t)(k * 136 + q * 4) * 4,
                     B + (size_t)(k0 + k) * ldb + colBase + q * 4);
            }
        } else {
#pragma unroll
            for (int e = 0; e < 16; e++) {
                int id = t + 256 * e;
                int k = id >> 7, n = id & 127;
                cp4(sB + st * B_STG + (uint32_t)(k * 136 + n) * 4,
                    B + (size_t)(k0 + k) * ldb + colBase + n);
            }
        }
    };

    issue(0, 0);
    CP_COMMIT;

    const int r0  = warpM * 32 + (lane >> 2);
    const int kq  = lane & 3;
    const int cl  = warpN * 64 + (lane >> 2);
    const uint32_t aBaseIdx = 0;          // float index of As
    const uint32_t bBaseIdx = SB_OFF / 4; // float index of Bs

    for (int kt = 0; kt < nkt; kt++) {
        if (kt + 1 < nkt) { issue((kt + 1) & 1, kt + 1); CP_COMMIT; CP_WAIT1; }
        else              { CP_WAIT0; }
        __syncthreads();

        const uint32_t aS = aBaseIdx + (kt & 1) * (A_STG / 4);
        const uint32_t bS = bBaseIdx + (kt & 1) * (B_STG / 4);
#pragma unroll
        for (int ks = 0; ks < 4; ks++) {
            const int kb = ks * 8;
            // A frags (+ optional lo residuals)
            uint32_t af[2][4], afl[2][4];
#pragma unroll
            for (int mt = 0; mt < 2; mt++) {
                int rr = r0 + mt * 16;
                float a0 = fs[aS + (rr    ) * 36 + kb + kq];
                float a1 = fs[aS + (rr + 8) * 36 + kb + kq];
                float a2 = fs[aS + (rr    ) * 36 + kb + kq + 4];
                float a3 = fs[aS + (rr + 8) * 36 + kb + kq + 4];
                float h0 = tf32r(a0), h1 = tf32r(a1), h2 = tf32r(a2), h3 = tf32r(a3);
                af[mt][0] = __float_as_uint(h0); af[mt][1] = __float_as_uint(h1);
                af[mt][2] = __float_as_uint(h2); af[mt][3] = __float_as_uint(h3);
                if (PRECISE) {
                    afl[mt][0] = __float_as_uint(tf32r(a0 - h0));
                    afl[mt][1] = __float_as_uint(tf32r(a1 - h1));
                    afl[mt][2] = __float_as_uint(tf32r(a2 - h2));
                    afl[mt][3] = __float_as_uint(tf32r(a3 - h3));
                }
            }
#pragma unroll
            for (int nt = 0; nt < 8; nt++) {
                int cc = cl + nt * 8;
                float b0 = fs[bS + (kb + kq    ) * 136 + cc];
                float b1 = fs[bS + (kb + kq + 4) * 136 + cc];
                float g0 = tf32r(b0), g1 = tf32r(b1);
                uint32_t bf[2] = { __float_as_uint(g0), __float_as_uint(g1) };
                if (PRECISE) {
                    uint32_t bfl[2] = { __float_as_uint(tf32r(b0 - g0)),
                                        __float_as_uint(tf32r(b1 - g1)) };
#pragma unroll
                    for (int mt = 0; mt < 2; mt++) {
                        mma8(acc[mt][nt], af[mt],  bfl);
                        mma8(acc[mt][nt], afl[mt], bf);
                        mma8(acc[mt][nt], af[mt],  bf);
                    }
                } else {
#pragma unroll
                    for (int mt = 0; mt < 2; mt++)
                        mma8(acc[mt][nt], af[mt], bf);
                }
            }
        }
        __syncthreads();
    }

    // ---- epilogue
    float* C = C0;
    int cbase = colBase;
    bool do_silu = false;
    int cstride = N;
    if (MODE == 1) {
        cstride = DINNER;
        if (colBase >= DINNER) { C = C1; cbase = colBase - DINNER; do_silu = true; }
    }

#pragma unroll
    for (int mt = 0; mt < 2; mt++) {
#pragma unroll
        for (int nt = 0; nt < 8; nt++) {
            int gr = rowBase + warpM * 32 + mt * 16 + (lane >> 2);
            int gc = cbase + warpN * 64 + nt * 8 + 2 * (lane & 3);
#pragma unroll
            for (int h = 0; h < 2; h++) {
                float v0 = acc[mt][nt][2 * h];
                float v1 = acc[mt][nt][2 * h + 1];
                int r = gr + h * 8;
                if (MODE == 1 && do_silu) {
                    v0 = v0 / (1.0f + expf(-v0));
                    v1 = v1 / (1.0f + expf(-v1));
                }
                if (MODE == 2) {
                    float2 a2 = *reinterpret_cast<const float2*>(aux + (size_t)r * N + gc);
                    v0 *= a2.x; v1 *= a2.y;
                }
                if (MODE == 3) {
                    atomicAdd(C + (size_t)r * cstride + gc,     v0);
                    atomicAdd(C + (size_t)r * cstride + gc + 1, v1);
                } else {
                    float2 o; o.x = v0; o.y = v1;
                    *reinterpret_cast<float2*>(C + (size_t)r * cstride + gc) = o;
                }
            }
        }
    }
}

// ---------------- delta: softplus(xi . W_xp[:,0]) -> A_bar ------------------
__global__ __launch_bounds__(256)
void delta_kernel(const float* __restrict__ xi, const float* __restrict__ W,
                  const float* __restrict__ A_log, float* __restrict__ ga)
{
    int m = blockIdx.x;
    const float* row = xi + (size_t)m * DINNER;
    float s = 0.0f;
    for (int k = threadIdx.x; k < DINNER; k += 256)
        s += row[k] * W[(size_t)k * NPROJ];
#pragma unroll
    for (int o = 16; o; o >>= 1) s += __shfl_xor_sync(0xFFFFFFFFu, s, o);
    __shared__ float red[8];
    if ((threadIdx.x & 31) == 0) red[threadIdx.x >> 5] = s;
    __syncthreads();
    if (threadIdx.x == 0) {
        float v = 0.0f;
#pragma unroll
        for (int i = 0; i < 8; i++) v += red[i];
        float sp = (v > 20.0f) ? v : log1pf(expf(v));
        ga[m] = expf(-expf(A_log[0]) * sp);
    }
}

// ---------------- parallel scan: 3 passes -----------------------------------
// prodA per (batch, chunk)
__global__ __launch_bounds__(128)
void prod_kernel()
{
    int b = blockIdx.x >> 4, c = blockIdx.x & 15;
    float v = g_a[b * SEQ + c * CHLEN + threadIdx.x];
#pragma unroll
    for (int o = 16; o; o >>= 1) v *= __shfl_xor_sync(0xFFFFFFFFu, v, o);
    __shared__ float red[4];
    if ((threadIdx.x & 31) == 0) red[threadIdx.x >> 5] = v;
    __syncthreads();
    if (threadIdx.x == 0)
        g_prodA[blockIdx.x] = red[0] * red[1] * red[2] * red[3];
}

// pass A: chunk-local scans (h0 = 0) -> g_hend
__global__ __launch_bounds__(256)
void scanA_kernel()
{
    int b = blockIdx.x >> 4, c = blockIdx.x & 15;
    int d = blockIdx.y * 256 + threadIdx.x;
    int s0 = c * CHLEN;
    float h = 0.0f;
    size_t base = ((size_t)b * SEQ + s0) * DINNER + d;
    int arow = b * SEQ + s0;
#pragma unroll 4
    for (int i = 0; i < CHLEN; i++)
        h = fmaf(g_a[arow + i], h, g_bx[base + (size_t)i * DINNER]);
    g_hend[(size_t)(b * NCH + c) * DINNER + d] = h;
}

// pass B: carries across chunks (16-step serial, fully parallel over channels)
__global__ __launch_bounds__(256)
void scanB_kernel()
{
    int b = blockIdx.x >> 3;
    int d = (blockIdx.x & 7) * 256 + threadIdx.x;
    float carry = 0.0f;
#pragma unroll
    for (int c = 0; c < NCH; c++) {
        size_t idx = (size_t)(b * NCH + c) * DINNER + d;
        g_carry[idx] = carry;
        carry = g_hend[idx] + g_prodA[b * NCH + c] * carry;
    }
}

// pass C: re-scan with carry + fused y = (C*h + D*xi)*silu(z)
__global__ __launch_bounds__(256)
void scanC_kernel(const float* __restrict__ D)
{
    int b = blockIdx.x >> 4, c = blockIdx.x & 15;
    int d = blockIdx.y * 256 + threadIdx.x;
    int s0 = c * CHLEN;
    float Dd = D[d];
    float h = g_carry[(size_t)(b * NCH + c) * DINNER + d];
    size_t base = ((size_t)b * SEQ + s0) * DINNER + d;
    int arow = b * SEQ + s0;
#pragma unroll 4
    for (int i = 0; i < CHLEN; i++) {
        size_t idx = base + (size_t)i * DINNER;
        float xi = g_xi[idx];
        h = fmaf(g_a[arow + i], h, g_bx[idx]);
        float y = fmaf(g_Cm[idx], h, Dd * xi);
        g_y[idx] = y * g_sz[idx];
    }
}

// ---------------- launch ----------------------------------------------------
extern "C" void kernel_launch(void* const* d_in, const int* in_sizes, int n_in,
                              void* d_out, int out_size)
{
    const float* x     = (const float*)d_in[0];
    const float* W_in  = (const float*)d_in[1];
    const float* W_xp  = (const float*)d_in[2];
    const float* W_B   = (const float*)d_in[3];
    const float* W_C   = (const float*)d_in[4];
    const float* W_out = (const float*)d_in[5];
    const float* Dvec  = (const float*)d_in[6];
    const float* A_log = (const float*)d_in[7];
    float* out = (float*)d_out;

    float *p_xi, *p_sz, *p_bx, *p_Cm, *p_y, *p_pBC, *p_a;
    cudaGetSymbolAddress((void**)&p_xi,  g_xi);
    cudaGetSymbolAddress((void**)&p_sz,  g_sz);
    cudaGetSymbolAddress((void**)&p_bx,  g_bx);
    cudaGetSymbolAddress((void**)&p_Cm,  g_Cm);
    cudaGetSymbolAddress((void**)&p_y,   g_y);
    cudaGetSymbolAddress((void**)&p_pBC, g_pBC);
    cudaGetSymbolAddress((void**)&p_a,   g_a);

    cudaFuncSetAttribute(gemm_cp<0,false,true>, cudaFuncAttributeMaxDynamicSharedMemorySize, GEMM_SMEM);
    cudaFuncSetAttribute(gemm_cp<1,false,true>, cudaFuncAttributeMaxDynamicSharedMemorySize, GEMM_SMEM);
    cudaFuncSetAttribute(gemm_cp<2,true,true>,  cudaFuncAttributeMaxDynamicSharedMemorySize, GEMM_SMEM);
    cudaFuncSetAttribute(gemm_cp<0,true,true>,  cudaFuncAttributeMaxDynamicSharedMemorySize, GEMM_SMEM);
    cudaFuncSetAttribute(gemm_cp<3,true,false>, cudaFuncAttributeMaxDynamicSharedMemorySize, GEMM_SMEM);

    // 1) xz = x @ W_in, fused split -> xi, silu(z)
    gemm_cp<1,false,true><<<dim3(32, 64), 256, GEMM_SMEM>>>(
        x, DMODEL, W_in, 2 * DINNER, p_xi, p_sz, nullptr, 2 * DINNER, DMODEL);

    // 2) delta column -> A_bar
    delta_kernel<<<MROWS, 256>>>(p_xi, W_xp, A_log, p_a);

    // 3) [B_raw|C_raw] = xi @ W_xp[:,1:129]  (split-K x4, atomic, 3xtf32)
    cudaMemsetAsync(p_pBC, 0, (size_t)MROWS * 128 * sizeof(float), 0);
    gemm_cp<3,true,false><<<dim3(1, 64, 4), 256, GEMM_SMEM>>>(
        p_xi, DINNER, W_xp + 1, NPROJ, p_pBC, nullptr, nullptr, 128, DINNER / 4);

    // 4) bx = (B_raw @ W_B) * xi    (3xtf32)
    gemm_cp<2,true,true><<<dim3(16, 64), 256, GEMM_SMEM>>>(
        p_pBC, 128, W_B, DINNER, p_bx, nullptr, p_xi, DINNER, DSTATE);

    // 5) Cm = C_raw @ W_C           (3xtf32)
    gemm_cp<0,true,true><<<dim3(16, 64), 256, GEMM_SMEM>>>(
        p_pBC + 64, 128, W_C, DINNER, p_Cm, nullptr, nullptr, DINNER, DSTATE);

    // 6) parallel scan
    prod_kernel<<<BATCH * NCH, 128>>>();
    scanA_kernel<<<dim3(BATCH * NCH, DINNER / 256), 256>>>();
    scanB_kernel<<<BATCH * (DINNER / 256), 256>>>();
    scanC_kernel<<<dim3(BATCH * NCH, DINNER / 256), 256>>>(Dvec);

    // 7) out = y @ W_out
    gemm_cp<0,false,true><<<dim3(8, 64), 256, GEMM_SMEM>>>(
        p_y, DINNER, W_out, DMODEL, out, nullptr, nullptr, DMODEL, DINNER);
}